// round 7
// baseline (speedup 1.0000x reference)
#include <cuda_runtime.h>
#include <cuda_fp16.h>

// APRConv1x1, two K=32 HMMA GEMMs + select (proven core), R7 deltas:
//  - cp.async double-buffered warp-private smem stages (raw f32 x + sidx):
//    no prefetch registers, >1 iteration of memory lookahead.
//  - B-fragments built DIRECTLY from raw f32 smem (4 conflict-free LDS.32 +
//    cvt + slot-shift by s&1): no pack/STS/syncwarp/ldmatrix chain.
//  - __launch_bounds__(128,8): <=64 regs -> 32 warps/SM (was 18).

#define THREADS 128
#define XPITCH 160u          // row pitch: 40 words == 8 mod 32 -> LDS conflict-free
#define SIDX_OFF 2560u       // 16 * 160
#define STAGE_BYTES 2688u    // + 128 sidx, 16B aligned

__global__ __launch_bounds__(THREADS, 8)
void apr_mma4_kernel(const float* __restrict__ x,
                     const float* __restrict__ Wg,    // [16][16][4]
                     const float* __restrict__ bias,  // [16]
                     const int*   __restrict__ sidx,  // [P]
                     float* __restrict__ out,         // [B][16][N]
                     unsigned Nn, unsigned P)
{
    __shared__ __align__(16) char pipe[4][2][STAGE_BYTES];

    const int tid = threadIdx.x;
    const int wid = tid >> 5;
    const int l   = tid & 31;
    const int t   = l & 3;     // k-group / point-pair selector
    const int r   = l >> 2;    // o-row AND point-col (both l>>2)

    // ---- once: weight A-fragments (k = 2i + j; W~[o][2i+j] = Wg[o*64+4i+2h+j]) ----
    unsigned a[2][2][4];
#pragma unroll
    for (int h = 0; h < 2; h++)
#pragma unroll
        for (int ks = 0; ks < 2; ks++) {
            const int i0 = 8 * ks + t;
            const int i1 = 8 * ks + 4 + t;
            float2 w; __half2 hh;
            w = *(const float2*)(Wg + r * 64 + i0 * 4 + 2 * h);
            hh = __floats2half2_rn(w.x, w.y); a[h][ks][0] = *(unsigned*)&hh;
            w = *(const float2*)(Wg + (r + 8) * 64 + i0 * 4 + 2 * h);
            hh = __floats2half2_rn(w.x, w.y); a[h][ks][1] = *(unsigned*)&hh;
            w = *(const float2*)(Wg + r * 64 + i1 * 4 + 2 * h);
            hh = __floats2half2_rn(w.x, w.y); a[h][ks][2] = *(unsigned*)&hh;
            w = *(const float2*)(Wg + (r + 8) * 64 + i1 * 4 + 2 * h);
            hh = __floats2half2_rn(w.x, w.y); a[h][ks][3] = *(unsigned*)&hh;
        }
    const float br0 = __ldg(bias + r);
    const float br8 = __ldg(bias + r + 8);

    const unsigned wtiles = (P + 31) >> 5;
    const unsigned wstep  = (unsigned)gridDim.x * 4;
    const unsigned wt0    = (unsigned)blockIdx.x * 4 + wid;
    const unsigned sb0    = (unsigned)__cvta_generic_to_shared(pipe[wid][0]);

    const int srow = l >> 3;          // cp.async row sub-index
    const int sbo  = (l & 7) * 16;    // cp.async byte offset in row

    auto issue = [&](unsigned wt_i, int buf) {
        if (wt_i < wtiles) {
            unsigned wtb = wt_i * 32; if (wtb + 32 > P) wtb = P - 32;
            const unsigned b  = wtb >= Nn ? 1u : 0u;
            const unsigned n0 = wtb - b * Nn;
            const char* xs = (const char*)(x + (size_t)b * 16 * Nn + n0);
            const unsigned sbuf = sb0 + (unsigned)buf * STAGE_BYTES;
#pragma unroll
            for (int j = 0; j < 4; j++) {
                const int row = 4 * j + srow;
                const char* src = xs + (size_t)row * ((size_t)Nn * 4) + sbo;
                const unsigned dst = sbuf + (unsigned)row * XPITCH + (unsigned)sbo;
                asm volatile("cp.async.cg.shared.global [%0], [%1], 16;"
                             :: "r"(dst), "l"(src));
            }
            asm volatile("cp.async.ca.shared.global [%0], [%1], 4;"
                         :: "r"(sbuf + SIDX_OFF + (unsigned)l * 4),
                            "l"((const char*)(sidx + wtb + l)));
        }
        asm volatile("cp.async.commit_group;");
    };

    issue(wt0, 0);
    issue(wt0 + wstep, 1);

    int buf = 0;
    for (unsigned wt = wt0; wt < wtiles; wt += wstep, buf ^= 1) {
        asm volatile("cp.async.wait_group 1;");

        unsigned wtb = wt * 32; if (wtb + 32 > P) wtb = P - 32;
        const unsigned b  = wtb >= Nn ? 1u : 0u;
        const unsigned n0 = wtb - b * Nn;
        float* fo = out + (size_t)b * 16 * Nn + n0;
        const unsigned sbuf = sb0 + (unsigned)buf * STAGE_BYTES;

#pragma unroll
        for (int g = 0; g < 4; g++) {
            const unsigned nl = (unsigned)(8 * g + r);   // point col of this lane's B frag

            int s_n;
            asm volatile("ld.shared.b32 %0, [%1];" : "=r"(s_n)
                         : "r"(sbuf + SIDX_OFF + nl * 4));
            const unsigned sh = ((unsigned)s_n & 1u) << 4;

            float x0, x1, x2, x3;
            asm volatile("ld.shared.f32 %0, [%1];" : "=f"(x0)
                         : "r"(sbuf + (unsigned)t * XPITCH + nl * 4));
            asm volatile("ld.shared.f32 %0, [%1];" : "=f"(x1)
                         : "r"(sbuf + (unsigned)(t + 4) * XPITCH + nl * 4));
            asm volatile("ld.shared.f32 %0, [%1];" : "=f"(x2)
                         : "r"(sbuf + (unsigned)(t + 8) * XPITCH + nl * 4));
            asm volatile("ld.shared.f32 %0, [%1];" : "=f"(x3)
                         : "r"(sbuf + (unsigned)(t + 12) * XPITCH + nl * 4));

            const unsigned b0 = (unsigned)__half_as_ushort(__float2half(x0)) << sh;
            const unsigned b1 = (unsigned)__half_as_ushort(__float2half(x1)) << sh;
            const unsigned b2 = (unsigned)__half_as_ushort(__float2half(x2)) << sh;
            const unsigned b3 = (unsigned)__half_as_ushort(__float2half(x3)) << sh;

            float dl0 = br0, dl1 = br0, dl2 = br8, dl3 = br8;
            float dh0 = br0, dh1 = br0, dh2 = br8, dh3 = br8;

            asm volatile("mma.sync.aligned.m16n8k16.row.col.f32.f16.f16.f32 "
                "{%0,%1,%2,%3}, {%4,%5,%6,%7}, {%8,%9}, {%0,%1,%2,%3};"
                : "+f"(dl0), "+f"(dl1), "+f"(dl2), "+f"(dl3)
                : "r"(a[0][0][0]), "r"(a[0][0][1]), "r"(a[0][0][2]), "r"(a[0][0][3]),
                  "r"(b0), "r"(b1));
            asm volatile("mma.sync.aligned.m16n8k16.row.col.f32.f16.f16.f32 "
                "{%0,%1,%2,%3}, {%4,%5,%6,%7}, {%8,%9}, {%0,%1,%2,%3};"
                : "+f"(dl0), "+f"(dl1), "+f"(dl2), "+f"(dl3)
                : "r"(a[0][1][0]), "r"(a[0][1][1]), "r"(a[0][1][2]), "r"(a[0][1][3]),
                  "r"(b2), "r"(b3));
            asm volatile("mma.sync.aligned.m16n8k16.row.col.f32.f16.f16.f32 "
                "{%0,%1,%2,%3}, {%4,%5,%6,%7}, {%8,%9}, {%0,%1,%2,%3};"
                : "+f"(dh0), "+f"(dh1), "+f"(dh2), "+f"(dh3)
                : "r"(a[1][0][0]), "r"(a[1][0][1]), "r"(a[1][0][2]), "r"(a[1][0][3]),
                  "r"(b0), "r"(b1));
            asm volatile("mma.sync.aligned.m16n8k16.row.col.f32.f16.f16.f32 "
                "{%0,%1,%2,%3}, {%4,%5,%6,%7}, {%8,%9}, {%0,%1,%2,%3};"
                : "+f"(dh0), "+f"(dh1), "+f"(dh2), "+f"(dh3)
                : "r"(a[1][1][0]), "r"(a[1][1][1]), "r"(a[1][1][2]), "r"(a[1][1][3]),
                  "r"(b2), "r"(b3));

            // select by s>>1 of the two points this lane stores, write float2
            const unsigned p0 = (unsigned)(8 * g + 2 * t);
            int s0, s1;
            asm volatile("ld.shared.b32 %0, [%1];" : "=r"(s0)
                         : "r"(sbuf + SIDX_OFF + p0 * 4));
            asm volatile("ld.shared.b32 %0, [%1];" : "=r"(s1)
                         : "r"(sbuf + SIDX_OFF + p0 * 4 + 4));

            const float o0 = (s0 & 2) ? dh0 : dl0;
            const float o1 = (s1 & 2) ? dh1 : dl1;
            const float o2 = (s0 & 2) ? dh2 : dl2;
            const float o3 = (s1 & 2) ? dh3 : dl3;

            float* ob = fo + p0;
            *reinterpret_cast<float2*>(ob + (unsigned)r * Nn)       = make_float2(o0, o1);
            *reinterpret_cast<float2*>(ob + (unsigned)(r + 8) * Nn) = make_float2(o2, o3);
        }

        issue(wt + 2 * wstep, buf);
    }
}

extern "C" void kernel_launch(void* const* d_in, const int* in_sizes, int n_in,
                              void* d_out, int out_size)
{
    const float* x    = (const float*)d_in[0];   // [B, 16, N]
    const float* Wg   = (const float*)d_in[1];   // [16, 16, 4, 1, 1]
    const float* bias = (const float*)d_in[2];   // [16]
    const int*   sidx = (const int*)d_in[3];     // [B, N]

    float* out = (float*)d_out;

    const unsigned P  = (unsigned)in_sizes[3];   // B*N
    const unsigned Nn = P / 2;                   // B = 2

    const unsigned wtiles = (P + 31) / 32;
    unsigned blk = (wtiles + 3) / 4;
    if (blk > 1184) blk = 1184;                  // 8 CTAs x 148 SMs

    apr_mma4_kernel<<<blk, THREADS>>>(x, Wg, bias, sidx, out, Nn, P);
}

// round 8
// speedup vs baseline: 1.4600x; 1.4600x over previous
#include <cuda_runtime.h>
#include <cuda_fp16.h>

// APRConv1x1, two K=32 HMMA GEMMs + select (R5/R6 proven core).
// R8: 64-point warp tiles (LDG.64 -> 33 lines in flight/warp, was 17),
//     single-buffer pipeline (pack+STS current, THEN prefetch into same regs,
//     then compute from smem) -> ~80 regs -> 6 CTAs/SM (24 warps, was 18),
//     swizzle extended by row-bit2 so STS.128/ldmatrix stay conflict-free.

#define THREADS 128

__global__ __launch_bounds__(THREADS, 6)
void apr_mma5_kernel(const float* __restrict__ x,
                     const float* __restrict__ Wg,    // [16][16][4]
                     const float* __restrict__ bias,  // [16]
                     const int*   __restrict__ sidx,  // [P]
                     float* __restrict__ out,         // [B][16][N]
                     unsigned Nn, unsigned P)
{
    __shared__ __align__(16) char stage[4][4096];   // 32 rows x 128B per warp

    const int tid = threadIdx.x;
    const int wid = tid >> 5;
    const int l   = tid & 31;
    const int t   = l & 3;
    const int r   = l >> 2;

    // ---- once: weight A-fragments (k = 2i + j; W_h[o][2i+j] = Wg[o*64+4i+2h+j]) ----
    unsigned a[2][2][4];
#pragma unroll
    for (int h = 0; h < 2; h++)
#pragma unroll
        for (int ks = 0; ks < 2; ks++) {
            const int i0 = 8 * ks + t;
            const int i1 = 8 * ks + 4 + t;
            float2 w; __half2 hh;
            w = *(const float2*)(Wg + r * 64 + i0 * 4 + 2 * h);
            hh = __floats2half2_rn(w.x, w.y); a[h][ks][0] = *(unsigned*)&hh;
            w = *(const float2*)(Wg + (r + 8) * 64 + i0 * 4 + 2 * h);
            hh = __floats2half2_rn(w.x, w.y); a[h][ks][1] = *(unsigned*)&hh;
            w = *(const float2*)(Wg + r * 64 + i1 * 4 + 2 * h);
            hh = __floats2half2_rn(w.x, w.y); a[h][ks][2] = *(unsigned*)&hh;
            w = *(const float2*)(Wg + (r + 8) * 64 + i1 * 4 + 2 * h);
            hh = __floats2half2_rn(w.x, w.y); a[h][ks][3] = *(unsigned*)&hh;
        }
    const float br0 = __ldg(bias + r);
    const float br8 = __ldg(bias + r + 8);

    const unsigned wtiles = (P + 63) >> 6;
    const unsigned wstep  = (unsigned)gridDim.x * 4;
    unsigned wt = (unsigned)blockIdx.x * 4 + wid;
    if (wt >= wtiles) return;

    const unsigned sbase = (unsigned)__cvta_generic_to_shared(stage[wid]);

    // write-side lane constants (lane owns row l = points 2l, 2l+1)
    const unsigned permw = (((unsigned)l & 3u) << 1) | (((unsigned)l >> 2) & 1u);
    const unsigned waddr = sbase + ((unsigned)l << 7);
    // read-side lane constants
    const unsigned wrd   = ((unsigned)l & 7u) >> 1;
    const unsigned bsx   = ((((unsigned)l >> 3) << 1) + ((unsigned)l & 1u)) ^ (wrd << 1);
    const unsigned raddr0 = sbase + (wrd << 7);
    // store row offsets (constant across tiles)
    const unsigned ro  = (unsigned)r * Nn;
    const unsigned ro8 = (unsigned)(r + 8) * Nn;

    // ---- prologue: load tile wt (points 2l, 2l+1 for 16 channels) ----
    float2 fv[16]; int2 sv;
    {
        unsigned wtb = wt << 6; if (wtb + 64u > P) wtb = P - 64u;
        const unsigned b  = wtb >= Nn ? 1u : 0u;
        const unsigned n0 = wtb - b * Nn;
        const float* xp = x + (size_t)b * 16u * Nn + n0 + 2u * (unsigned)l;
#pragma unroll
        for (int i = 0; i < 16; i++)
            fv[i] = *reinterpret_cast<const float2*>(xp + (size_t)((unsigned)i * Nn));
        sv = *reinterpret_cast<const int2*>(sidx + wtb + 2u * (unsigned)l);
    }

    for (;;) {
        unsigned wtb = wt << 6; if (wtb + 64u > P) wtb = P - 64u;
        const unsigned b  = wtb >= Nn ? 1u : 0u;
        const unsigned n0 = wtb - b * Nn;
        float* fo = out + (size_t)b * 16u * Nn + n0;

        const int s_e = sv.x, s_o = sv.y;
        const unsigned sh_e = ((unsigned)s_e & 1u) << 4;
        const unsigned sh_o = ((unsigned)s_o & 1u) << 4;

        // ---- pack + stage current tile (8x STS.128, conflict-free) ----
#pragma unroll
        for (int cc = 0; cc < 4; cc++) {
            unsigned e0, e1, e2, e3, o0, o1, o2, o3;
            e0 = (unsigned)__half_as_ushort(__float2half(fv[4*cc+0].x)) << sh_e;
            e1 = (unsigned)__half_as_ushort(__float2half(fv[4*cc+1].x)) << sh_e;
            e2 = (unsigned)__half_as_ushort(__float2half(fv[4*cc+2].x)) << sh_e;
            e3 = (unsigned)__half_as_ushort(__float2half(fv[4*cc+3].x)) << sh_e;
            o0 = (unsigned)__half_as_ushort(__float2half(fv[4*cc+0].y)) << sh_o;
            o1 = (unsigned)__half_as_ushort(__float2half(fv[4*cc+1].y)) << sh_o;
            o2 = (unsigned)__half_as_ushort(__float2half(fv[4*cc+2].y)) << sh_o;
            o3 = (unsigned)__half_as_ushort(__float2half(fv[4*cc+3].y)) << sh_o;
            const unsigned ae = waddr + ((((unsigned)(2*cc))     ^ permw) << 4);
            const unsigned ao = waddr + ((((unsigned)(2*cc + 1)) ^ permw) << 4);
            asm volatile("st.shared.v4.b32 [%0], {%1,%2,%3,%4};"
                         :: "r"(ae), "r"(e0), "r"(e1), "r"(e2), "r"(e3));
            asm volatile("st.shared.v4.b32 [%0], {%1,%2,%3,%4};"
                         :: "r"(ao), "r"(o0), "r"(o1), "r"(o2), "r"(o3));
        }

        // ---- prefetch next tile into the SAME registers (WAR after pack) ----
        const unsigned wtn = wt + wstep;
        const bool more = wtn < wtiles;
        if (more) {
            unsigned wtb2 = wtn << 6; if (wtb2 + 64u > P) wtb2 = P - 64u;
            const unsigned b2 = wtb2 >= Nn ? 1u : 0u;
            const unsigned n2 = wtb2 - b2 * Nn;
            const float* xp = x + (size_t)b2 * 16u * Nn + n2 + 2u * (unsigned)l;
#pragma unroll
            for (int i = 0; i < 16; i++)
                fv[i] = *reinterpret_cast<const float2*>(xp + (size_t)((unsigned)i * Nn));
            sv = *reinterpret_cast<const int2*>(sidx + wtb2 + 2u * (unsigned)l);
        }
        __syncwarp();

        // ---- compute: 8 groups of 8 points ----
#pragma unroll
        for (int g = 0; g < 8; g++) {
            const unsigned addr = raddr0 + ((unsigned)g << 9)
                                + ((bsx ^ ((unsigned)g & 1u)) << 4);
            unsigned b0, b1, b2, b3;
            asm volatile("ldmatrix.sync.aligned.m8n8.x4.shared.b16 {%0,%1,%2,%3}, [%4];"
                         : "=r"(b0), "=r"(b1), "=r"(b2), "=r"(b3) : "r"(addr));

            float dl0 = br0, dl1 = br0, dl2 = br8, dl3 = br8;
            float dh0 = br0, dh1 = br0, dh2 = br8, dh3 = br8;

            asm volatile("mma.sync.aligned.m16n8k16.row.col.f32.f16.f16.f32 "
                "{%0,%1,%2,%3}, {%4,%5,%6,%7}, {%8,%9}, {%0,%1,%2,%3};"
                : "+f"(dl0), "+f"(dl1), "+f"(dl2), "+f"(dl3)
                : "r"(a[0][0][0]), "r"(a[0][0][1]), "r"(a[0][0][2]), "r"(a[0][0][3]),
                  "r"(b0), "r"(b1));
            asm volatile("mma.sync.aligned.m16n8k16.row.col.f32.f16.f16.f32 "
                "{%0,%1,%2,%3}, {%4,%5,%6,%7}, {%8,%9}, {%0,%1,%2,%3};"
                : "+f"(dl0), "+f"(dl1), "+f"(dl2), "+f"(dl3)
                : "r"(a[0][1][0]), "r"(a[0][1][1]), "r"(a[0][1][2]), "r"(a[0][1][3]),
                  "r"(b2), "r"(b3));
            asm volatile("mma.sync.aligned.m16n8k16.row.col.f32.f16.f16.f32 "
                "{%0,%1,%2,%3}, {%4,%5,%6,%7}, {%8,%9}, {%0,%1,%2,%3};"
                : "+f"(dh0), "+f"(dh1), "+f"(dh2), "+f"(dh3)
                : "r"(a[1][0][0]), "r"(a[1][0][1]), "r"(a[1][0][2]), "r"(a[1][0][3]),
                  "r"(b0), "r"(b1));
            asm volatile("mma.sync.aligned.m16n8k16.row.col.f32.f16.f16.f32 "
                "{%0,%1,%2,%3}, {%4,%5,%6,%7}, {%8,%9}, {%0,%1,%2,%3};"
                : "+f"(dh0), "+f"(dh1), "+f"(dh2), "+f"(dh3)
                : "r"(a[1][1][0]), "r"(a[1][1][1]), "r"(a[1][1][2]), "r"(a[1][1][3]),
                  "r"(b2), "r"(b3));

            // select: s of points (8g+2t, 8g+2t+1) lives in lane 4g+t (current tile regs)
            const int src = 4 * g + t;
            const int ss0 = __shfl_sync(0xffffffffu, s_e, src);
            const int ss1 = __shfl_sync(0xffffffffu, s_o, src);
            const float q0 = (ss0 & 2) ? dh0 : dl0;
            const float q1 = (ss1 & 2) ? dh1 : dl1;
            const float q2 = (ss0 & 2) ? dh2 : dl2;
            const float q3 = (ss1 & 2) ? dh3 : dl3;

            const unsigned p0 = (unsigned)(8 * g + 2 * t);
            *reinterpret_cast<float2*>(fo + ro  + p0) = make_float2(q0, q1);
            *reinterpret_cast<float2*>(fo + ro8 + p0) = make_float2(q2, q3);
        }
        __syncwarp();   // ldmatrix reads done before next iteration's STS

        if (!more) break;
        wt = wtn;
    }
}

extern "C" void kernel_launch(void* const* d_in, const int* in_sizes, int n_in,
                              void* d_out, int out_size)
{
    const float* x    = (const float*)d_in[0];   // [B, 16, N]
    const float* Wg   = (const float*)d_in[1];   // [16, 16, 4, 1, 1]
    const float* bias = (const float*)d_in[2];   // [16]
    const int*   sidx = (const int*)d_in[3];     // [B, N]

    float* out = (float*)d_out;

    const unsigned P  = (unsigned)in_sizes[3];   // B*N
    const unsigned Nn = P / 2;                   // B = 2

    const unsigned wtiles = (P + 63) / 64;
    unsigned blk = (wtiles + 3) / 4;
    if (blk > 888) blk = 888;                    // 6 CTAs x 148 SMs, persistent

    apr_mma5_kernel<<<blk, THREADS>>>(x, Wg, bias, sidx, out, Nn, P);
}